// round 3
// baseline (speedup 1.0000x reference)
#include <cuda_runtime.h>
#include <cuda_bf16.h>

// DynamicMaskHead (CondInst mask head) for GB300.
// Fixed problem shapes: N=2 images, Cin=8, H=100, W=152, n_inst=400,
// stride=8 -> factor=2, out = [400, 1, 200, 304] float32.

#define HH 100
#define WW 152
#define HWP (HH * WW)          // 15200 (divisible by 4)
#define NPARAM 169
#define MAXINST 400
#define OH (2 * HH)            // 200
#define OW (2 * WW)            // 304

// Scratch: per-instance logits at feature resolution. 400*15200*4B = 24.3 MB.
__device__ float g_logits[MAXINST * HWP];

__device__ __forceinline__ float2 ffma2(float2 a, float2 b, float2 c) {
    float2 d;
    asm("fma.rn.f32x2 %0, %1, %2, %3;"
        : "=l"(reinterpret_cast<unsigned long long &>(d))
        : "l"(reinterpret_cast<unsigned long long &>(a)),
          "l"(reinterpret_cast<unsigned long long &>(b)),
          "l"(reinterpret_cast<unsigned long long &>(c)));
    return d;
}

__device__ __forceinline__ float2 relu2(float2 a) {
    return make_float2(fmaxf(a.x, 0.0f), fmaxf(a.y, 0.0f));
}

// ---------------------------------------------------------------------------
// Kernel A: per-instance dynamic 3-layer MLP over all feature pixels.
// Grid: (15 groups-of-1024-px tiles, n_inst). Block: 256 threads.
// Each thread owns 4 CONSECUTIVE pixels -> feature gather is one LDG.128 per
// channel (coalesced across the warp) and the logits write is one STG.128.
// The 4 pixels are packed as 2 f32x2 lanes so the MLP runs on FFMA2.
// Weights are pre-duplicated into float2 pairs in shared: one broadcast
// LDS.64 per weight in the mainloop, no per-thread register duplication.
// ---------------------------------------------------------------------------
__global__ void __launch_bounds__(256)
mlp_kernel(const float* __restrict__ feats,      // [2, 8, H, W]
           const float* __restrict__ params,     // [n_inst, 169]
           const float* __restrict__ ilocs,      // [n_inst, 2]
           const int*   __restrict__ im_inds,    // [n_inst]
           const int*   __restrict__ fpn)        // [n_inst]
{
    __shared__ float2 w2s[NPARAM];
    __shared__ float s_locx, s_locy, s_invsoi;
    __shared__ int   s_base;

    const int inst = blockIdx.y;
    const int tid  = threadIdx.x;

    if (tid < NPARAM) {
        float ww = params[inst * NPARAM + tid];
        w2s[tid] = make_float2(ww, ww);
    }
    if (tid == 0) {
        s_locx = ilocs[inst * 2 + 0];
        s_locy = ilocs[inst * 2 + 1];
        int lvl = fpn[inst];
        // SOI = 64 * 2^lvl (exact powers of two -> reciprocal-multiply exact)
        s_invsoi = 1.0f / (64.0f * (float)(1 << lvl));
        s_base = im_inds[inst] * 8 * HWP;
    }
    __syncthreads();

    const float locx = s_locx, locy = s_locy, invsoi = s_invsoi;
    const int base = s_base;

    // Group of 4 consecutive pixels. HWP % 4 == 0 -> group is all-in or all-out.
    const int p0 = (blockIdx.x * 256 + tid) * 4;
    if (p0 >= HWP) return;

    // Gather the 10 MLP inputs per pixel: [rel_x, rel_y, f0..f7]
    float a[4][10];
    {
        int py = p0 / WW;
        int px = p0 % WW;
#pragma unroll
        for (int k = 0; k < 4; k++) {
            a[k][0] = (locx - (float)(px * 8 + 4)) * invsoi;
            a[k][1] = (locy - (float)(py * 8 + 4)) * invsoi;
            if (++px == WW) { px = 0; py++; }
        }
    }
#pragma unroll
    for (int c = 0; c < 8; c++) {
        float4 f = *reinterpret_cast<const float4*>(&feats[base + c * HWP + p0]);
        a[0][2 + c] = f.x;
        a[1][2 + c] = f.y;
        a[2][2 + c] = f.z;
        a[3][2 + c] = f.w;
    }

    float2 in0[10], in1[10];
#pragma unroll
    for (int i = 0; i < 10; i++) {
        in0[i] = make_float2(a[0][i], a[1][i]);
        in1[i] = make_float2(a[2][i], a[3][i]);
    }

    // Layer 0: 8 x 10 + bias, ReLU.  w0[o][i] = w[o*10+i], b0[o] = w[152+o]
    float2 h0[8], h1[8];
#pragma unroll
    for (int o = 0; o < 8; o++) {
        float2 bias = w2s[152 + o];
        float2 acc0 = bias;
        float2 acc1 = bias;
#pragma unroll
        for (int i = 0; i < 10; i++) {
            float2 wv = w2s[o * 10 + i];
            acc0 = ffma2(in0[i], wv, acc0);
            acc1 = ffma2(in1[i], wv, acc1);
        }
        h0[o] = relu2(acc0);
        h1[o] = relu2(acc1);
    }

    // Layer 1: 8 x 8 + bias, ReLU.  w1[o][i] = w[80+o*8+i], b1[o] = w[160+o]
    float2 g0[8], g1[8];
#pragma unroll
    for (int o = 0; o < 8; o++) {
        float2 bias = w2s[160 + o];
        float2 acc0 = bias;
        float2 acc1 = bias;
#pragma unroll
        for (int i = 0; i < 8; i++) {
            float2 wv = w2s[80 + o * 8 + i];
            acc0 = ffma2(h0[i], wv, acc0);
            acc1 = ffma2(h1[i], wv, acc1);
        }
        g0[o] = relu2(acc0);
        g1[o] = relu2(acc1);
    }

    // Layer 2: 1 x 8 + bias.  w2[i] = w[144+i], b2 = w[168]
    float2 o0 = w2s[168];
    float2 o1 = o0;
#pragma unroll
    for (int i = 0; i < 8; i++) {
        float2 wv = w2s[144 + i];
        o0 = ffma2(g0[i], wv, o0);
        o1 = ffma2(g1[i], wv, o1);
    }

    *reinterpret_cast<float4*>(&g_logits[inst * HWP + p0]) =
        make_float4(o0.x, o0.y, o1.x, o1.y);
}

// ---------------------------------------------------------------------------
// Kernel B: aligned_bilinear, factor=2 (AdelaiDet semantics).
// For output (y, x): iy=max(y-1,0), ix=max(x-1,0); y0=iy>>1, fy=(iy&1)*0.5;
// x0=ix>>1, fx=(ix&1)*0.5; clamp y0+1<=H-1, x0+1<=W-1.
// Each thread produces the pair (x=2u, x=2u+1):
//   x=2u+1 -> ix even -> fx=0 -> pure row-interp at column u      = c(u)
//   x=2u   -> ix odd (or 0)    -> 0.5*(c(u-1)+c(u)) (u=0: c(0))
// float2 store (2u is even -> 8B aligned).
// ---------------------------------------------------------------------------
__global__ void __launch_bounds__(256)
upsample_kernel(float* __restrict__ out, int n_inst)
{
    int idx = blockIdx.x * blockDim.x + threadIdx.x;
    int total = n_inst * OH * WW;     // one thread per (n, y, u) with u in [0,152)
    if (idx >= total) return;

    int u = idx % WW;
    int t = idx / WW;
    int y = t % OH;
    int n = t / OH;

    int iy = max(y - 1, 0);
    int y0 = iy >> 1;
    float fy = (iy & 1) ? 0.5f : 0.0f;
    int y1 = min(y0 + 1, HH - 1);

    const float* tb = g_logits + n * HWP;
    const float* r0 = tb + y0 * WW;
    const float* r1 = tb + y1 * WW;

    int up = max(u - 1, 0);
    float c0 = r0[up] * (1.0f - fy) + r1[up] * fy;   // column interp at u-1
    float c1 = r0[u]  * (1.0f - fy) + r1[u]  * fy;   // column interp at u

    float2 val;
    val.x = 0.5f * (c0 + c1);   // at u==0, c0==c1 -> exact c(0)
    val.y = c1;

    float2* op = reinterpret_cast<float2*>(out + (size_t)n * (OH * OW) + y * OW);
    op[u] = val;
}

extern "C" void kernel_launch(void* const* d_in, const int* in_sizes, int n_in,
                              void* d_out, int out_size)
{
    const float* feats   = (const float*)d_in[0];   // mask_feats [2,8,100,152]
    const float* params  = (const float*)d_in[1];   // [n_inst, 169]
    const float* ilocs   = (const float*)d_in[2];   // [n_inst, 2]
    const int*   im_inds = (const int*)d_in[3];     // [n_inst]
    const int*   fpn     = (const int*)d_in[4];     // [n_inst]

    int n_inst = in_sizes[3];
    if (n_inst > MAXINST) n_inst = MAXINST;

    dim3 gridA((HWP / 4 + 255) / 256, n_inst);
    mlp_kernel<<<gridA, 256>>>(feats, params, ilocs, im_inds, fpn);

    int totalB = n_inst * OH * WW;
    int gridB = (totalB + 255) / 256;
    upsample_kernel<<<gridB, 256>>>((float*)d_out, n_inst);
}